// round 3
// baseline (speedup 1.0000x reference)
#include <cuda_runtime.h>
#include <cuda_bf16.h>
#include <cstddef>

// Problem constants (fixed shapes from setup_inputs)
#define B_    2
#define S_    4096
#define D_    1024
#define HEADS 16
#define DH    64
#define SEG   512
#define P_    16
#define NW    (S_ / SEG)         // 8
#define INNER (HEADS * DH)       // 1024
#define NQKV  (3 * INNER)        // 3072
#define ROWS  (B_ * S_)          // 8192
#define T_    (SEG + P_)         // 528

// Scratch (device globals — no allocation inside kernel_launch)
__device__ float g_h[(size_t)ROWS * D_];       // 32 MB
__device__ float g_qkv[(size_t)ROWS * NQKV];   // 96 MB
__device__ float g_attn[(size_t)ROWS * INNER]; // 32 MB

// ---------------------------------------------------------------------------
// RMSNorm: one block (256 thr) per row of 1024
// ---------------------------------------------------------------------------
__global__ void rmsnorm_kernel(const float* __restrict__ x,
                               const float* __restrict__ gamma,
                               float* __restrict__ h) {
    int row = blockIdx.x;
    const float* xr = x + (size_t)row * D_;
    float* hr = h + (size_t)row * D_;
    int t = threadIdx.x;

    float v[4];
    float ss = 0.f;
#pragma unroll
    for (int i = 0; i < 4; i++) {
        v[i] = xr[t + i * 256];
        ss += v[i] * v[i];
    }
    __shared__ float red[8];
#pragma unroll
    for (int o = 16; o; o >>= 1) ss += __shfl_xor_sync(0xffffffffu, ss, o);
    if ((t & 31) == 0) red[t >> 5] = ss;
    __syncthreads();
    if (t < 32) {
        float s2 = (t < 8) ? red[t] : 0.f;
#pragma unroll
        for (int o = 4; o; o >>= 1) s2 += __shfl_xor_sync(0xffffffffu, s2, o);
        if (t == 0) red[0] = s2;
    }
    __syncthreads();
    float inv = rsqrtf(red[0] * (1.0f / D_) + 1e-6f);
#pragma unroll
    for (int i = 0; i < 4; i++)
        hr[t + i * 256] = v[i] * inv * gamma[t + i * 256];
}

// ---------------------------------------------------------------------------
// SGEMM: C[M,N] = A[M,K] @ B[K,N], 128x128x8 tile, 8x8 per-thread, 256 thr.
// Double-buffered smem: global loads for tile k+1 are issued before the
// compute phase of tile k, so the ~L2/DRAM latency overlaps 512 FFMAs.
// ---------------------------------------------------------------------------
__global__ __launch_bounds__(256, 2)
void sgemm128_kernel(const float* __restrict__ A,
                     const float* __restrict__ Bm,
                     float* __restrict__ C,
                     int M, int N, int K) {
    __shared__ float As[2][8][128];
    __shared__ float Bs[2][8][128];

    int tid = threadIdx.x;
    int bx = blockIdx.x, by = blockIdx.y;
    int tx = tid % 16, ty = tid / 16;
    int row0 = by * 128 + ty * 8;
    int col0 = bx * 128 + tx * 8;

    int aRow = tid >> 1;
    int aCol = (tid & 1) * 4;
    int bRow = tid >> 5;
    int bCol = (tid & 31) * 4;

    const float* Aptr = A + (size_t)(by * 128 + aRow) * K + aCol;
    const float* Bptr = Bm + (size_t)bRow * N + bx * 128 + bCol;

    float acc[8][8];
#pragma unroll
    for (int i = 0; i < 8; i++)
#pragma unroll
        for (int j = 0; j < 8; j++) acc[i][j] = 0.f;

    // Preload tile 0
    float4 av = *(const float4*)(Aptr);
    float4 bv = *(const float4*)(Bptr);
    As[0][aCol + 0][aRow] = av.x;
    As[0][aCol + 1][aRow] = av.y;
    As[0][aCol + 2][aRow] = av.z;
    As[0][aCol + 3][aRow] = av.w;
    *(float4*)&Bs[0][bRow][bCol] = bv;
    __syncthreads();

    for (int kt = 0; kt < K; kt += 8) {
        int cur = (kt >> 3) & 1;
        bool has_next = (kt + 8) < K;
        if (has_next) {
            av = *(const float4*)(Aptr + kt + 8);
            bv = *(const float4*)(Bptr + (size_t)(kt + 8) * N);
        }

#pragma unroll
        for (int kk = 0; kk < 8; kk++) {
            float a[8], bb[8];
#pragma unroll
            for (int i = 0; i < 8; i++) a[i] = As[cur][kk][ty * 8 + i];
#pragma unroll
            for (int j = 0; j < 8; j++) bb[j] = Bs[cur][kk][tx * 8 + j];
#pragma unroll
            for (int i = 0; i < 8; i++)
#pragma unroll
                for (int j = 0; j < 8; j++) acc[i][j] += a[i] * bb[j];
        }

        if (has_next) {
            int nxt = cur ^ 1;
            As[nxt][aCol + 0][aRow] = av.x;
            As[nxt][aCol + 1][aRow] = av.y;
            As[nxt][aCol + 2][aRow] = av.z;
            As[nxt][aCol + 3][aRow] = av.w;
            *(float4*)&Bs[nxt][bRow][bCol] = bv;
            __syncthreads();
        }
    }

#pragma unroll
    for (int i = 0; i < 8; i++) {
        float4* cp = (float4*)&C[(size_t)(row0 + i) * N + col0];
        cp[0] = make_float4(acc[i][0], acc[i][1], acc[i][2], acc[i][3]);
        cp[1] = make_float4(acc[i][4], acc[i][5], acc[i][6], acc[i][7]);
    }
}

// ---------------------------------------------------------------------------
// Attention: block handles 64 q-rows of one (b,w,h) tile. Full 528-col score
// row lives in smem (no online softmax). 256 threads, 4x4 microtiles.
// Dynamic smem: q[64][64] + kv[64][65] + scores[64][532] = 169216 B
// ---------------------------------------------------------------------------
#define QC 64
#define SC_STRIDE 532
#define ATTN_SMEM ((64 * 64 + 64 * 65 + 64 * SC_STRIDE) * sizeof(float))

__global__ __launch_bounds__(256, 1)
void attn_kernel(const float* __restrict__ qkv,
                 const float* __restrict__ pm_k,
                 const float* __restrict__ pm_v,
                 float* __restrict__ out) {
    extern __shared__ float sm[];
    float* sq = sm;                  // [64][64]
    float* skv = sm + 64 * 64;       // [64][65]
    float* sc = skv + 64 * 65;       // [64][SC_STRIDE]

    int tile = blockIdx.x;
    int h = tile % HEADS;
    int w = (tile / HEADS) % NW;
    int b = tile / (HEADS * NW);
    int q0 = blockIdx.y * QC;
    int tid = threadIdx.x;
    int tx = tid % 16, ty = tid / 16;
    int r0 = ty * 4, c0 = tx * 4;

    const float scale = 0.125f;  // 1/sqrt(64)

    // Load Q chunk (scale folded in)
    for (int idx = tid; idx < QC * DH; idx += 256) {
        int r = idx >> 6, d = idx & 63;
        int s = w * SEG + q0 + r;
        sq[r * 64 + d] = qkv[((size_t)(b * S_ + s)) * NQKV + h * DH + d] * scale;
    }
    __syncthreads();

    // Phase B: scores = Q K^T
    for (int chunk = 0; chunk < 9; chunk++) {
        int j0 = chunk * 64;
        int jmax = min(64, T_ - j0);
        for (int idx = tid; idx < 64 * DH; idx += 256) {
            int jj = idx >> 6, d = idx & 63;
            float val = 0.f;
            int j = j0 + jj;
            if (jj < jmax) {
                if (j < P_) {
                    val = pm_k[(h * P_ + j) * DH + d];
                } else {
                    int s = w * SEG + (j - P_);
                    val = qkv[((size_t)(b * S_ + s)) * NQKV + INNER + h * DH + d];
                }
            }
            skv[jj * 65 + d] = val;
        }
        __syncthreads();

        float acc[4][4] = {};
#pragma unroll 8
        for (int d = 0; d < 64; d++) {
            float a[4], kb[4];
#pragma unroll
            for (int i = 0; i < 4; i++) a[i] = sq[(r0 + i) * 64 + d];
#pragma unroll
            for (int k = 0; k < 4; k++) kb[k] = skv[(c0 + k) * 65 + d];
#pragma unroll
            for (int i = 0; i < 4; i++)
#pragma unroll
                for (int k = 0; k < 4; k++) acc[i][k] += a[i] * kb[k];
        }
#pragma unroll
        for (int i = 0; i < 4; i++)
#pragma unroll
            for (int k = 0; k < 4; k++) {
                int j = j0 + c0 + k;
                if (j < T_) sc[(r0 + i) * SC_STRIDE + j] = acc[i][k];
            }
        __syncthreads();
    }

    // Phase C: masked softmax per row. Warp handles 8 consecutive rows.
    int warp = tid >> 5, lane = tid & 31;
    for (int rr = 0; rr < 8; rr++) {
        int r = warp * 8 + rr;
        int qi = q0 + r;
        int cnt = qi + P_ + 1;  // keys j in [0, cnt) are unmasked (j <= qi+P)
        float m = -1e30f;
        for (int j = lane; j < cnt; j += 32) m = fmaxf(m, sc[r * SC_STRIDE + j]);
#pragma unroll
        for (int o = 16; o; o >>= 1) m = fmaxf(m, __shfl_xor_sync(0xffffffffu, m, o));
        float ssum = 0.f;
        for (int j = lane; j < cnt; j += 32) {
            float e = __expf(sc[r * SC_STRIDE + j] - m);
            sc[r * SC_STRIDE + j] = e;
            ssum += e;
        }
#pragma unroll
        for (int o = 16; o; o >>= 1) ssum += __shfl_xor_sync(0xffffffffu, ssum, o);
        float inv = 1.f / ssum;
        for (int j = lane; j < cnt; j += 32) sc[r * SC_STRIDE + j] *= inv;
        for (int j = cnt + lane; j < T_; j += 32) sc[r * SC_STRIDE + j] = 0.f;
    }
    __syncthreads();

    // Phase D: out = P @ V
    float oacc[4][4] = {};
    for (int chunk = 0; chunk < 9; chunk++) {
        int j0 = chunk * 64;
        int jmax = min(64, T_ - j0);
        for (int idx = tid; idx < 64 * DH; idx += 256) {
            int jj = idx >> 6, d = idx & 63;
            float val = 0.f;
            int j = j0 + jj;
            if (jj < jmax) {
                if (j < P_) {
                    val = pm_v[(h * P_ + j) * DH + d];
                } else {
                    int s = w * SEG + (j - P_);
                    val = qkv[((size_t)(b * S_ + s)) * NQKV + 2 * INNER + h * DH + d];
                }
            }
            skv[jj * 65 + d] = val;
        }
        __syncthreads();
        for (int jj = 0; jj < jmax; jj++) {
            float p[4], vv[4];
#pragma unroll
            for (int i = 0; i < 4; i++) p[i] = sc[(r0 + i) * SC_STRIDE + j0 + jj];
#pragma unroll
            for (int k = 0; k < 4; k++) vv[k] = skv[jj * 65 + c0 + k];
#pragma unroll
            for (int i = 0; i < 4; i++)
#pragma unroll
                for (int k = 0; k < 4; k++) oacc[i][k] += p[i] * vv[k];
        }
        __syncthreads();
    }

#pragma unroll
    for (int i = 0; i < 4; i++) {
        float4* op = (float4*)&out[((size_t)(b * S_ + w * SEG + q0 + r0 + i)) * INNER + h * DH + c0];
        *op = make_float4(oacc[i][0], oacc[i][1], oacc[i][2], oacc[i][3]);
    }
}

// ---------------------------------------------------------------------------
// Launch
// ---------------------------------------------------------------------------
extern "C" void kernel_launch(void* const* d_in, const int* in_sizes, int n_in,
                              void* d_out, int out_size) {
    (void)in_sizes; (void)n_in; (void)out_size;
    const float* x      = (const float*)d_in[0];
    const float* gamma  = (const float*)d_in[1];
    const float* w_qkv  = (const float*)d_in[2];
    const float* w_out  = (const float*)d_in[3];
    const float* pm_k   = (const float*)d_in[4];
    const float* pm_v   = (const float*)d_in[5];
    float* out = (float*)d_out;

    float *h_ptr, *qkv_ptr, *attn_ptr;
    cudaGetSymbolAddress((void**)&h_ptr, g_h);
    cudaGetSymbolAddress((void**)&qkv_ptr, g_qkv);
    cudaGetSymbolAddress((void**)&attn_ptr, g_attn);

    cudaFuncSetAttribute(attn_kernel,
                         cudaFuncAttributeMaxDynamicSharedMemorySize,
                         (int)ATTN_SMEM);

    // 1. RMSNorm
    rmsnorm_kernel<<<ROWS, 256>>>(x, gamma, h_ptr);

    // 2. QKV projection: [8192,1024] @ [1024,3072]
    {
        dim3 grid(NQKV / 128, ROWS / 128);
        sgemm128_kernel<<<grid, 256>>>(h_ptr, w_qkv, qkv_ptr, ROWS, NQKV, D_);
    }

    // 3. Attention
    {
        dim3 grid(B_ * NW * HEADS, SEG / QC);
        attn_kernel<<<grid, 256, ATTN_SMEM>>>(qkv_ptr, pm_k, pm_v, attn_ptr);
    }

    // 4. Output projection: [8192,1024] @ [1024,1024]
    {
        dim3 grid(D_ / 128, ROWS / 128);
        sgemm128_kernel<<<grid, 256>>>(attn_ptr, w_out, out, ROWS, D_, INNER);
    }
}

// round 9
// speedup vs baseline: 1.3223x; 1.3223x over previous
#include <cuda_runtime.h>
#include <cuda_bf16.h>
#include <cstdint>
#include <cstddef>

// Problem constants (fixed shapes)
#define B_    2
#define S_    4096
#define D_    1024
#define HEADS 16
#define DH    64
#define SEG   512
#define P_    16
#define NW    (S_ / SEG)         // 8
#define INNER (HEADS * DH)       // 1024
#define NQKV  (3 * INNER)        // 3072
#define ROWS  (B_ * S_)          // 8192
#define T_    (SEG + P_)         // 528

// ---------------------------------------------------------------------------
// Scratch (device globals)
// ---------------------------------------------------------------------------
__device__ __nv_bfloat16 g_h_hi[(size_t)ROWS * D_];
__device__ __nv_bfloat16 g_h_lo[(size_t)ROWS * D_];
__device__ __nv_bfloat16 g_wqkvT_hi[(size_t)NQKV * D_];   // [N=3072, K=1024]
__device__ __nv_bfloat16 g_wqkvT_lo[(size_t)NQKV * D_];
__device__ __nv_bfloat16 g_woutT_hi[(size_t)D_ * INNER];  // [N=1024, K=1024]
__device__ __nv_bfloat16 g_woutT_lo[(size_t)D_ * INNER];
__device__ float         g_qkv[(size_t)ROWS * NQKV];      // 96 MB fp32
__device__ __nv_bfloat16 g_attn_hi[(size_t)ROWS * INNER];
__device__ __nv_bfloat16 g_attn_lo[(size_t)ROWS * INNER];

// ---------------------------------------------------------------------------
// mma.sync m16n8k16 bf16 (row.col) — portable to compute_103
// ---------------------------------------------------------------------------
#define MMA16816(d, a0, a1, a2, a3, b0, b1) \
    asm volatile( \
        "mma.sync.aligned.m16n8k16.row.col.f32.bf16.bf16.f32 " \
        "{%0,%1,%2,%3}, {%4,%5,%6,%7}, {%8,%9}, {%0,%1,%2,%3};" \
        : "+f"((d)[0]), "+f"((d)[1]), "+f"((d)[2]), "+f"((d)[3]) \
        : "r"(a0), "r"(a1), "r"(a2), "r"(a3), "r"(b0), "r"(b1))

// ---------------------------------------------------------------------------
// RMSNorm -> bf16 hi/lo split
// ---------------------------------------------------------------------------
__global__ void rmsnorm_split_kernel(const float* __restrict__ x,
                                     const float* __restrict__ gamma,
                                     __nv_bfloat16* __restrict__ hhi,
                                     __nv_bfloat16* __restrict__ hlo) {
    int row = blockIdx.x;
    const float* xr = x + (size_t)row * D_;
    int t = threadIdx.x;

    float v[4];
    float ss = 0.f;
#pragma unroll
    for (int i = 0; i < 4; i++) {
        v[i] = xr[t + i * 256];
        ss += v[i] * v[i];
    }
    __shared__ float red[8];
#pragma unroll
    for (int o = 16; o; o >>= 1) ss += __shfl_xor_sync(0xffffffffu, ss, o);
    if ((t & 31) == 0) red[t >> 5] = ss;
    __syncthreads();
    if (t < 32) {
        float s2 = (t < 8) ? red[t] : 0.f;
#pragma unroll
        for (int o = 4; o; o >>= 1) s2 += __shfl_xor_sync(0xffffffffu, s2, o);
        if (t == 0) red[0] = s2;
    }
    __syncthreads();
    float inv = rsqrtf(red[0] * (1.0f / D_) + 1e-6f);
#pragma unroll
    for (int i = 0; i < 4; i++) {
        int idx = t + i * 256;
        float y = v[i] * inv * gamma[idx];
        __nv_bfloat16 hi = __float2bfloat16(y);
        float lof = y - __bfloat162float(hi);
        hhi[(size_t)row * D_ + idx] = hi;
        hlo[(size_t)row * D_ + idx] = __float2bfloat16(lof);
    }
}

// ---------------------------------------------------------------------------
// Weight transpose + split: W[K,N] fp32 -> Th/Tl[N,K] bf16
// ---------------------------------------------------------------------------
__global__ void transpose_split_kernel(const float* __restrict__ W,
                                       __nv_bfloat16* __restrict__ Th,
                                       __nv_bfloat16* __restrict__ Tl,
                                       int K, int N) {
    __shared__ float t[32][33];
    int n0 = blockIdx.x * 32, k0 = blockIdx.y * 32;
    int tx = threadIdx.x, ty = threadIdx.y;
#pragma unroll
    for (int i = 0; i < 4; i++) {
        int k = ty + i * 8;
        t[k][tx] = W[(size_t)(k0 + k) * N + n0 + tx];
    }
    __syncthreads();
#pragma unroll
    for (int i = 0; i < 4; i++) {
        int n = ty + i * 8;
        float val = t[tx][n];
        __nv_bfloat16 hi = __float2bfloat16(val);
        float lof = val - __bfloat162float(hi);
        Th[(size_t)(n0 + n) * K + k0 + tx] = hi;
        Tl[(size_t)(n0 + n) * K + k0 + tx] = __float2bfloat16(lof);
    }
}

// ---------------------------------------------------------------------------
// Split-bf16 GEMM via mma.sync: C[M,N] fp32 = A[M,K] @ B, B given as
// B^T[N,K] (both hi/lo bf16, K-major). CTA tile 128x128, 8 warps, warp tile
// 64x32, K chunk 32, double-buffered padded smem (stride 40 bf16).
// Virtual passes over K: (Ah,Bh), (Ah,Bl), (Al,Bh).
// ---------------------------------------------------------------------------
#define GK      1024
#define KC2     32
#define NCHUNK2 (3 * GK / KC2)   // 96
#define SSTR    40               // smem row stride in bf16 (pad 8)

__global__ __launch_bounds__(256, 2)
void gemm_mma_kernel(const __nv_bfloat16* __restrict__ Ah,
                     const __nv_bfloat16* __restrict__ Al,
                     const __nv_bfloat16* __restrict__ Bh,
                     const __nv_bfloat16* __restrict__ Bl,
                     float* __restrict__ C, int N) {
    __shared__ __align__(16) __nv_bfloat16 sA[2][128 * SSTR];
    __shared__ __align__(16) __nv_bfloat16 sB[2][128 * SSTR];

    int tid = threadIdx.x;
    int wid = tid >> 5, lane = tid & 31;
    int wm = wid >> 2, wn = wid & 3;       // warp grid 2x4
    int row0 = blockIdx.y * 128;
    int col0 = blockIdx.x * 128;
    int g = lane >> 2, tg = lane & 3;

    float acc[4][4][4];
#pragma unroll
    for (int mi = 0; mi < 4; mi++)
#pragma unroll
        for (int ni = 0; ni < 4; ni++)
#pragma unroll
            for (int q = 0; q < 4; q++) acc[mi][ni][q] = 0.f;

    // Global load slots: 512 uint4 per matrix per chunk, 2 per thread.
    int lr[2], lc[2];
#pragma unroll
    for (int i = 0; i < 2; i++) {
        int e = tid + i * 256;
        lr[i] = e >> 2;          // row within tile (0..127)
        lc[i] = (e & 3) * 8;     // k offset in bf16 (0,8,16,24)
    }

    uint4 ra[2], rb[2];
    {
        const __nv_bfloat16* Ap = Ah;
        const __nv_bfloat16* Bp = Bh;
#pragma unroll
        for (int i = 0; i < 2; i++) {
            ra[i] = *(const uint4*)(Ap + (size_t)(row0 + lr[i]) * GK + lc[i]);
            rb[i] = *(const uint4*)(Bp + (size_t)(col0 + lr[i]) * GK + lc[i]);
        }
    }

    for (int chunk = 0; chunk < NCHUNK2; chunk++) {
        int buf = chunk & 1;
#pragma unroll
        for (int i = 0; i < 2; i++) {
            *(uint4*)&sA[buf][lr[i] * SSTR + lc[i]] = ra[i];
            *(uint4*)&sB[buf][lr[i] * SSTR + lc[i]] = rb[i];
        }
        __syncthreads();

        // Prefetch next chunk (overlaps the MMAs below)
        int nc = chunk + 1;
        if (nc < NCHUNK2) {
            int part = nc >> 5;
            int k0 = (nc & 31) * KC2;
            const __nv_bfloat16* Ap = (part == 2) ? Al : Ah;
            const __nv_bfloat16* Bp = (part == 1) ? Bl : Bh;
#pragma unroll
            for (int i = 0; i < 2; i++) {
                ra[i] = *(const uint4*)(Ap + (size_t)(row0 + lr[i]) * GK + k0 + lc[i]);
                rb[i] = *(const uint4*)(Bp + (size_t)(col0 + lr[i]) * GK + k0 + lc[i]);
            }
        }

        // Compute: 2 k-substeps of 16
        const __nv_bfloat16* pA = sA[buf];
        const __nv_bfloat16* pB = sB[buf];
#pragma unroll
        for (int ks = 0; ks < KC2; ks += 16) {
            uint32_t afr[4][4];
#pragma unroll
            for (int mi = 0; mi < 4; mi++) {
                int m = wm * 64 + mi * 16;
                afr[mi][0] = *(const uint32_t*)&pA[(m + g) * SSTR + ks + tg * 2];
                afr[mi][1] = *(const uint32_t*)&pA[(m + g + 8) * SSTR + ks + tg * 2];
                afr[mi][2] = *(const uint32_t*)&pA[(m + g) * SSTR + ks + 8 + tg * 2];
                afr[mi][3] = *(const uint32_t*)&pA[(m + g + 8) * SSTR + ks + 8 + tg * 2];
            }
            uint32_t bfr[4][2];
#pragma unroll
            for (int ni = 0; ni < 4; ni++) {
                int n = wn * 32 + ni * 8;
                bfr[ni][0] = *(const uint32_t*)&pB[(n + g) * SSTR + ks + tg * 2];
                bfr[ni][1] = *(const uint32_t*)&pB[(n + g) * SSTR + ks + 8 + tg * 2];
            }
#pragma unroll
            for (int mi = 0; mi < 4; mi++)
#pragma unroll
                for (int ni = 0; ni < 4; ni++)
                    MMA16816(acc[mi][ni], afr[mi][0], afr[mi][1], afr[mi][2],
                             afr[mi][3], bfr[ni][0], bfr[ni][1]);
        }
        // No extra barrier needed: next iteration writes the other buffer,
        // and its __syncthreads() orders compute(c) before store(c+2).
    }

    // Epilogue: per-fragment f32 stores (2 x float2 per fragment per thread)
#pragma unroll
    for (int mi = 0; mi < 4; mi++) {
        int m = row0 + wm * 64 + mi * 16;
#pragma unroll
        for (int ni = 0; ni < 4; ni++) {
            int n = col0 + wn * 32 + ni * 8;
            float2* p0 = (float2*)&C[(size_t)(m + g) * N + n + tg * 2];
            float2* p1 = (float2*)&C[(size_t)(m + g + 8) * N + n + tg * 2];
            *p0 = make_float2(acc[mi][ni][0], acc[mi][ni][1]);
            *p1 = make_float2(acc[mi][ni][2], acc[mi][ni][3]);
        }
    }
}

// ---------------------------------------------------------------------------
// Attention: QC=32 q-rows per block (93KB smem -> 2 CTAs/SM).
// Epilogue writes bf16 hi/lo for the tensor-core out-projection.
// ---------------------------------------------------------------------------
#define QC 32
#define SC_STRIDE 532
#define ATTN_SMEM ((QC * 64 + 64 * 65 + QC * SC_STRIDE) * sizeof(float))

__global__ __launch_bounds__(256, 2)
void attn_kernel(const float* __restrict__ qkv,
                 const float* __restrict__ pm_k,
                 const float* __restrict__ pm_v,
                 __nv_bfloat16* __restrict__ ohi,
                 __nv_bfloat16* __restrict__ olo) {
    extern __shared__ float sm[];
    float* sq = sm;                    // [QC][64]
    float* skv = sm + QC * 64;         // [64][65]
    float* sc = skv + 64 * 65;         // [QC][SC_STRIDE]

    int tile = blockIdx.x;
    int h = tile % HEADS;
    int w = (tile / HEADS) % NW;
    int b = tile / (HEADS * NW);
    int q0 = blockIdx.y * QC;
    int tid = threadIdx.x;
    int tx = tid % 16, ty = tid / 16;
    int r0 = ty * 2, c0 = tx * 4;

    const float scale = 0.125f;

    for (int idx = tid; idx < QC * DH; idx += 256) {
        int r = idx >> 6, d = idx & 63;
        int s = w * SEG + q0 + r;
        sq[r * 64 + d] = qkv[((size_t)(b * S_ + s)) * NQKV + h * DH + d] * scale;
    }
    __syncthreads();

    // scores = Q K^T
    for (int chunk = 0; chunk < 9; chunk++) {
        int j0 = chunk * 64;
        int jmax = min(64, T_ - j0);
        for (int idx = tid; idx < 64 * DH; idx += 256) {
            int jj = idx >> 6, d = idx & 63;
            float val = 0.f;
            int j = j0 + jj;
            if (jj < jmax) {
                if (j < P_) {
                    val = pm_k[(h * P_ + j) * DH + d];
                } else {
                    int s = w * SEG + (j - P_);
                    val = qkv[((size_t)(b * S_ + s)) * NQKV + INNER + h * DH + d];
                }
            }
            skv[jj * 65 + d] = val;
        }
        __syncthreads();

        float acc[2][4] = {};
#pragma unroll 8
        for (int d = 0; d < 64; d++) {
            float a[2], kb[4];
#pragma unroll
            for (int i = 0; i < 2; i++) a[i] = sq[(r0 + i) * 64 + d];
#pragma unroll
            for (int k = 0; k < 4; k++) kb[k] = skv[(c0 + k) * 65 + d];
#pragma unroll
            for (int i = 0; i < 2; i++)
#pragma unroll
                for (int k = 0; k < 4; k++) acc[i][k] += a[i] * kb[k];
        }
#pragma unroll
        for (int i = 0; i < 2; i++)
#pragma unroll
            for (int k = 0; k < 4; k++) {
                int j = j0 + c0 + k;
                if (j < T_) sc[(r0 + i) * SC_STRIDE + j] = acc[i][k];
            }
        __syncthreads();
    }

    // masked softmax; each warp handles 4 rows
    int warp = tid >> 5, lane = tid & 31;
    for (int rr = 0; rr < 4; rr++) {
        int r = warp * 4 + rr;
        int qi = q0 + r;
        int cnt = qi + P_ + 1;
        float m = -1e30f;
        for (int j = lane; j < cnt; j += 32) m = fmaxf(m, sc[r * SC_STRIDE + j]);
#pragma unroll
        for (int o = 16; o; o >>= 1) m = fmaxf(m, __shfl_xor_sync(0xffffffffu, m, o));
        float ssum = 0.f;
        for (int j = lane; j < cnt; j += 32) {
            float e = __expf(sc[r * SC_STRIDE + j] - m);
            sc[r * SC_STRIDE + j] = e;
            ssum += e;
        }
#pragma unroll
        for (int o = 16; o; o >>= 1) ssum += __shfl_xor_sync(0xffffffffu, ssum, o);
        float inv = 1.f / ssum;
        for (int j = lane; j < cnt; j += 32) sc[r * SC_STRIDE + j] *= inv;
        for (int j = cnt + lane; j < T_; j += 32) sc[r * SC_STRIDE + j] = 0.f;
    }
    __syncthreads();

    // out = P @ V
    float oacc[2][4] = {};
    for (int chunk = 0; chunk < 9; chunk++) {
        int j0 = chunk * 64;
        int jmax = min(64, T_ - j0);
        for (int idx = tid; idx < 64 * DH; idx += 256) {
            int jj = idx >> 6, d = idx & 63;
            float val = 0.f;
            int j = j0 + jj;
            if (jj < jmax) {
                if (j < P_) {
                    val = pm_v[(h * P_ + j) * DH + d];
                } else {
                    int s = w * SEG + (j - P_);
                    val = qkv[((size_t)(b * S_ + s)) * NQKV + 2 * INNER + h * DH + d];
                }
            }
            skv[jj * 65 + d] = val;
        }
        __syncthreads();
        for (int jj = 0; jj < jmax; jj++) {
            float p[2], vv[4];
#pragma unroll
            for (int i = 0; i < 2; i++) p[i] = sc[(r0 + i) * SC_STRIDE + j0 + jj];
#pragma unroll
            for (int k = 0; k < 4; k++) vv[k] = skv[jj * 65 + c0 + k];
#pragma unroll
            for (int i = 0; i < 2; i++)
#pragma unroll
                for (int k = 0; k < 4; k++) oacc[i][k] += p[i] * vv[k];
        }
        __syncthreads();
    }

#pragma unroll
    for (int i = 0; i < 2; i++) {
        size_t base = ((size_t)(b * S_ + w * SEG + q0 + r0 + i)) * INNER + h * DH + c0;
#pragma unroll
        for (int k = 0; k < 4; k++) {
            float o = oacc[i][k];
            __nv_bfloat16 hi = __float2bfloat16(o);
            float lof = o - __bfloat162float(hi);
            ohi[base + k] = hi;
            olo[base + k] = __float2bfloat16(lof);
        }
    }
}

// ---------------------------------------------------------------------------
// Launch
// ---------------------------------------------------------------------------
extern "C" void kernel_launch(void* const* d_in, const int* in_sizes, int n_in,
                              void* d_out, int out_size) {
    (void)in_sizes; (void)n_in; (void)out_size;
    const float* x      = (const float*)d_in[0];
    const float* gamma  = (const float*)d_in[1];
    const float* w_qkv  = (const float*)d_in[2];
    const float* w_out  = (const float*)d_in[3];
    const float* pm_k   = (const float*)d_in[4];
    const float* pm_v   = (const float*)d_in[5];
    float* out = (float*)d_out;

    __nv_bfloat16 *h_hi, *h_lo, *wq_hi, *wq_lo, *wo_hi, *wo_lo, *a_hi, *a_lo;
    float* qkv_ptr;
    cudaGetSymbolAddress((void**)&h_hi, g_h_hi);
    cudaGetSymbolAddress((void**)&h_lo, g_h_lo);
    cudaGetSymbolAddress((void**)&wq_hi, g_wqkvT_hi);
    cudaGetSymbolAddress((void**)&wq_lo, g_wqkvT_lo);
    cudaGetSymbolAddress((void**)&wo_hi, g_woutT_hi);
    cudaGetSymbolAddress((void**)&wo_lo, g_woutT_lo);
    cudaGetSymbolAddress((void**)&a_hi, g_attn_hi);
    cudaGetSymbolAddress((void**)&a_lo, g_attn_lo);
    cudaGetSymbolAddress((void**)&qkv_ptr, g_qkv);

    cudaFuncSetAttribute(attn_kernel,
                         cudaFuncAttributeMaxDynamicSharedMemorySize,
                         (int)ATTN_SMEM);

    // Weight prep (transpose + bf16 split)
    {
        dim3 blk(32, 8);
        dim3 g1(NQKV / 32, D_ / 32);
        transpose_split_kernel<<<g1, blk>>>(w_qkv, wq_hi, wq_lo, D_, NQKV);
        dim3 g2(D_ / 32, INNER / 32);
        transpose_split_kernel<<<g2, blk>>>(w_out, wo_hi, wo_lo, INNER, D_);
    }

    // RMSNorm + split
    rmsnorm_split_kernel<<<ROWS, 256>>>(x, gamma, h_hi, h_lo);

    // QKV projection (mma.sync tensor cores): [8192,1024] @ [1024,3072]
    {
        dim3 grid(NQKV / 128, ROWS / 128);
        gemm_mma_kernel<<<grid, 256>>>(h_hi, h_lo, wq_hi, wq_lo, qkv_ptr, NQKV);
    }

    // Attention
    {
        dim3 grid(B_ * NW * HEADS, SEG / QC);
        attn_kernel<<<grid, 256, ATTN_SMEM>>>(qkv_ptr, pm_k, pm_v, a_hi, a_lo);
    }

    // Output projection (mma.sync tensor cores): [8192,1024] @ [1024,1024]
    {
        dim3 grid(D_ / 128, ROWS / 128);
        gemm_mma_kernel<<<grid, 256>>>(a_hi, a_lo, wo_hi, wo_lo, out, D_);
    }
}

// round 15
// speedup vs baseline: 3.2625x; 2.4673x over previous
#include <cuda_runtime.h>
#include <cuda_bf16.h>
#include <cstdint>
#include <cstddef>

// Problem constants (fixed shapes)
#define B_    2
#define S_    4096
#define D_    1024
#define HEADS 16
#define DH    64
#define SEG   512
#define P_    16
#define NW    (S_ / SEG)         // 8
#define INNER (HEADS * DH)       // 1024
#define NQKV  (3 * INNER)        // 3072
#define ROWS  (B_ * S_)          // 8192
#define T_    (SEG + P_)         // 528

// ---------------------------------------------------------------------------
// Scratch (device globals)
// ---------------------------------------------------------------------------
__device__ __nv_bfloat16 g_h_hi[(size_t)ROWS * D_];
__device__ __nv_bfloat16 g_h_lo[(size_t)ROWS * D_];
__device__ __nv_bfloat16 g_wqkvT_hi[(size_t)NQKV * D_];   // [N=3072, K=1024]
__device__ __nv_bfloat16 g_wqkvT_lo[(size_t)NQKV * D_];
__device__ __nv_bfloat16 g_woutT_hi[(size_t)D_ * INNER];  // [N=1024, K=1024]
__device__ __nv_bfloat16 g_woutT_lo[(size_t)D_ * INNER];
__device__ __nv_bfloat16 g_qkv_hi[(size_t)ROWS * NQKV];   // bf16 hi (Q scaled)
__device__ __nv_bfloat16 g_qkv_lo[(size_t)ROWS * NQKV];   // bf16 lo
__device__ __nv_bfloat16 g_vt_hi[(size_t)B_ * HEADS * DH * S_]; // V^T [b,h,d,s]
__device__ __nv_bfloat16 g_vt_lo[(size_t)B_ * HEADS * DH * S_];
__device__ __nv_bfloat16 g_pmvt_hi[HEADS * DH * P_];      // pm_v^T [h,d,p]
__device__ __nv_bfloat16 g_pmvt_lo[HEADS * DH * P_];
__device__ __nv_bfloat16 g_attn_hi[(size_t)ROWS * INNER];
__device__ __nv_bfloat16 g_attn_lo[(size_t)ROWS * INNER];

// ---------------------------------------------------------------------------
// mma.sync m16n8k16 bf16 (row.col) — portable to compute_103
// ---------------------------------------------------------------------------
#define MMA16816(d, a0, a1, a2, a3, b0, b1) \
    asm volatile( \
        "mma.sync.aligned.m16n8k16.row.col.f32.bf16.bf16.f32 " \
        "{%0,%1,%2,%3}, {%4,%5,%6,%7}, {%8,%9}, {%0,%1,%2,%3};" \
        : "+f"((d)[0]), "+f"((d)[1]), "+f"((d)[2]), "+f"((d)[3]) \
        : "r"(a0), "r"(a1), "r"(a2), "r"(a3), "r"(b0), "r"(b1))

__device__ __forceinline__ uint32_t packbf(float a, float b) {
    unsigned short lo = __bfloat16_as_ushort(__float2bfloat16(a));
    unsigned short hi = __bfloat16_as_ushort(__float2bfloat16(b));
    return (uint32_t)lo | ((uint32_t)hi << 16);
}

// Split 8 fp32 into hi/lo bf16 uint4s
__device__ __forceinline__ void split8(const float* f, uint4& vh, uint4& vl) {
    float hi[8], lo[8];
#pragma unroll
    for (int i = 0; i < 8; i++) {
        __nv_bfloat16 hb = __float2bfloat16(f[i]);
        hi[i] = __bfloat162float(hb);
        lo[i] = f[i] - hi[i];
    }
    vh.x = packbf(hi[0], hi[1]); vh.y = packbf(hi[2], hi[3]);
    vh.z = packbf(hi[4], hi[5]); vh.w = packbf(hi[6], hi[7]);
    vl.x = packbf(lo[0], lo[1]); vl.y = packbf(lo[2], lo[3]);
    vl.z = packbf(lo[4], lo[5]); vl.w = packbf(lo[6], lo[7]);
}

// ---------------------------------------------------------------------------
// RMSNorm -> bf16 hi/lo split
// ---------------------------------------------------------------------------
__global__ void rmsnorm_split_kernel(const float* __restrict__ x,
                                     const float* __restrict__ gamma,
                                     __nv_bfloat16* __restrict__ hhi,
                                     __nv_bfloat16* __restrict__ hlo) {
    int row = blockIdx.x;
    const float* xr = x + (size_t)row * D_;
    int t = threadIdx.x;

    float v[4];
    float ss = 0.f;
#pragma unroll
    for (int i = 0; i < 4; i++) {
        v[i] = xr[t + i * 256];
        ss += v[i] * v[i];
    }
    __shared__ float red[8];
#pragma unroll
    for (int o = 16; o; o >>= 1) ss += __shfl_xor_sync(0xffffffffu, ss, o);
    if ((t & 31) == 0) red[t >> 5] = ss;
    __syncthreads();
    if (t < 32) {
        float s2 = (t < 8) ? red[t] : 0.f;
#pragma unroll
        for (int o = 4; o; o >>= 1) s2 += __shfl_xor_sync(0xffffffffu, s2, o);
        if (t == 0) red[0] = s2;
    }
    __syncthreads();
    float inv = rsqrtf(red[0] * (1.0f / D_) + 1e-6f);
#pragma unroll
    for (int i = 0; i < 4; i++) {
        int idx = t + i * 256;
        float y = v[i] * inv * gamma[idx];
        __nv_bfloat16 hi = __float2bfloat16(y);
        float lof = y - __bfloat162float(hi);
        hhi[(size_t)row * D_ + idx] = hi;
        hlo[(size_t)row * D_ + idx] = __float2bfloat16(lof);
    }
}

// ---------------------------------------------------------------------------
// Weight transpose + split: W[K,N] fp32 -> Th/Tl[N,K] bf16
// ---------------------------------------------------------------------------
__global__ void transpose_split_kernel(const float* __restrict__ W,
                                       __nv_bfloat16* __restrict__ Th,
                                       __nv_bfloat16* __restrict__ Tl,
                                       int K, int N) {
    __shared__ float t[32][33];
    int n0 = blockIdx.x * 32, k0 = blockIdx.y * 32;
    int tx = threadIdx.x, ty = threadIdx.y;
#pragma unroll
    for (int i = 0; i < 4; i++) {
        int k = ty + i * 8;
        t[k][tx] = W[(size_t)(k0 + k) * N + n0 + tx];
    }
    __syncthreads();
#pragma unroll
    for (int i = 0; i < 4; i++) {
        int n = ty + i * 8;
        float val = t[tx][n];
        __nv_bfloat16 hi = __float2bfloat16(val);
        float lof = val - __bfloat162float(hi);
        Th[(size_t)(n0 + n) * K + k0 + tx] = hi;
        Tl[(size_t)(n0 + n) * K + k0 + tx] = __float2bfloat16(lof);
    }
}

// ---------------------------------------------------------------------------
// pm_v transpose + split: [h][p][d] fp32 -> [h][d][p] bf16 hi/lo
// ---------------------------------------------------------------------------
__global__ void pmvt_kernel(const float* __restrict__ pm_v,
                            __nv_bfloat16* __restrict__ th,
                            __nv_bfloat16* __restrict__ tl) {
    int idx = blockIdx.x * 256 + threadIdx.x;
    if (idx >= HEADS * P_ * DH) return;
    int h = idx / (P_ * DH);
    int rem = idx % (P_ * DH);
    int p = rem / DH, d = rem % DH;
    float v = pm_v[idx];
    __nv_bfloat16 hb = __float2bfloat16(v);
    float lo = v - __bfloat162float(hb);
    th[(h * DH + d) * P_ + p] = hb;
    tl[(h * DH + d) * P_ + p] = __float2bfloat16(lo);
}

// ---------------------------------------------------------------------------
// Split-bf16 GEMM via mma.sync. Mainloop identical to the validated R9 kernel.
// MODE 0: fp32 C out (out-projection). MODE 1: bf16 hi/lo out with Q-scale
// and transposed V region (QKV projection).
// ---------------------------------------------------------------------------
#define GK      1024
#define KC2     32
#define NCHUNK2 (3 * GK / KC2)   // 96
#define SSTR    40               // smem row stride in bf16 (pad 8)

template <int MODE>
__global__ __launch_bounds__(256, 2)
void gemm_mma_kernel(const __nv_bfloat16* __restrict__ Ah,
                     const __nv_bfloat16* __restrict__ Al,
                     const __nv_bfloat16* __restrict__ Bh,
                     const __nv_bfloat16* __restrict__ Bl,
                     float* __restrict__ C,
                     __nv_bfloat16* __restrict__ Chi,
                     __nv_bfloat16* __restrict__ Clo,
                     __nv_bfloat16* __restrict__ Vth,
                     __nv_bfloat16* __restrict__ Vtl,
                     int N) {
    __shared__ __align__(16) __nv_bfloat16 sA[2][128 * SSTR];
    __shared__ __align__(16) __nv_bfloat16 sB[2][128 * SSTR];

    int tid = threadIdx.x;
    int wid = tid >> 5, lane = tid & 31;
    int wm = wid >> 2, wn = wid & 3;       // warp grid 2x4
    int row0 = blockIdx.y * 128;
    int col0 = blockIdx.x * 128;
    int g = lane >> 2, tg = lane & 3;

    float acc[4][4][4];
#pragma unroll
    for (int mi = 0; mi < 4; mi++)
#pragma unroll
        for (int ni = 0; ni < 4; ni++)
#pragma unroll
            for (int q = 0; q < 4; q++) acc[mi][ni][q] = 0.f;

    int lr[2], lc[2];
#pragma unroll
    for (int i = 0; i < 2; i++) {
        int e = tid + i * 256;
        lr[i] = e >> 2;
        lc[i] = (e & 3) * 8;
    }

    uint4 ra[2], rb[2];
    {
#pragma unroll
        for (int i = 0; i < 2; i++) {
            ra[i] = *(const uint4*)(Ah + (size_t)(row0 + lr[i]) * GK + lc[i]);
            rb[i] = *(const uint4*)(Bh + (size_t)(col0 + lr[i]) * GK + lc[i]);
        }
    }

    for (int chunk = 0; chunk < NCHUNK2; chunk++) {
        int buf = chunk & 1;
#pragma unroll
        for (int i = 0; i < 2; i++) {
            *(uint4*)&sA[buf][lr[i] * SSTR + lc[i]] = ra[i];
            *(uint4*)&sB[buf][lr[i] * SSTR + lc[i]] = rb[i];
        }
        __syncthreads();

        int nc = chunk + 1;
        if (nc < NCHUNK2) {
            int part = nc >> 5;
            int k0 = (nc & 31) * KC2;
            const __nv_bfloat16* Ap = (part == 2) ? Al : Ah;
            const __nv_bfloat16* Bp = (part == 1) ? Bl : Bh;
#pragma unroll
            for (int i = 0; i < 2; i++) {
                ra[i] = *(const uint4*)(Ap + (size_t)(row0 + lr[i]) * GK + k0 + lc[i]);
                rb[i] = *(const uint4*)(Bp + (size_t)(col0 + lr[i]) * GK + k0 + lc[i]);
            }
        }

        const __nv_bfloat16* pA = sA[buf];
        const __nv_bfloat16* pB = sB[buf];
#pragma unroll
        for (int ks = 0; ks < KC2; ks += 16) {
            uint32_t afr[4][4];
#pragma unroll
            for (int mi = 0; mi < 4; mi++) {
                int m = wm * 64 + mi * 16;
                afr[mi][0] = *(const uint32_t*)&pA[(m + g) * SSTR + ks + tg * 2];
                afr[mi][1] = *(const uint32_t*)&pA[(m + g + 8) * SSTR + ks + tg * 2];
                afr[mi][2] = *(const uint32_t*)&pA[(m + g) * SSTR + ks + 8 + tg * 2];
                afr[mi][3] = *(const uint32_t*)&pA[(m + g + 8) * SSTR + ks + 8 + tg * 2];
            }
            uint32_t bfr[4][2];
#pragma unroll
            for (int ni = 0; ni < 4; ni++) {
                int n = wn * 32 + ni * 8;
                bfr[ni][0] = *(const uint32_t*)&pB[(n + g) * SSTR + ks + tg * 2];
                bfr[ni][1] = *(const uint32_t*)&pB[(n + g) * SSTR + ks + 8 + tg * 2];
            }
#pragma unroll
            for (int mi = 0; mi < 4; mi++)
#pragma unroll
                for (int ni = 0; ni < 4; ni++)
                    MMA16816(acc[mi][ni], afr[mi][0], afr[mi][1], afr[mi][2],
                             afr[mi][3], bfr[ni][0], bfr[ni][1]);
        }
    }

    // Epilogue
#pragma unroll
    for (int mi = 0; mi < 4; mi++) {
        int m = row0 + wm * 64 + mi * 16;
#pragma unroll
        for (int ni = 0; ni < 4; ni++) {
            int n0 = col0 + wn * 32 + ni * 8 + tg * 2;
#pragma unroll
            for (int rh = 0; rh < 2; rh++) {
                int mr = m + g + rh * 8;
                float v0 = acc[mi][ni][rh * 2 + 0];
                float v1 = acc[mi][ni][rh * 2 + 1];
                if (MODE == 0) {
                    *(float2*)&C[(size_t)mr * N + n0] = make_float2(v0, v1);
                } else {
                    if (n0 < INNER) { v0 *= 0.125f; v1 *= 0.125f; }
                    __nv_bfloat16 h0 = __float2bfloat16(v0);
                    __nv_bfloat16 h1 = __float2bfloat16(v1);
                    float l0f = v0 - __bfloat162float(h0);
                    float l1f = v1 - __bfloat162float(h1);
                    if (n0 < 2 * INNER) {
                        *(uint32_t*)&Chi[(size_t)mr * NQKV + n0] =
                            packbf(__bfloat162float(h0), __bfloat162float(h1));
                        *(uint32_t*)&Clo[(size_t)mr * NQKV + n0] = packbf(l0f, l1f);
                    } else {
                        int hh = (n0 - 2 * INNER) >> 6;
                        int d = (n0 - 2 * INNER) & 63;
                        int bb = mr >> 12;          // / S_
                        int s = mr & (S_ - 1);
                        size_t base = ((size_t)((bb * HEADS + hh) * DH + d)) * S_ + s;
                        Vth[base] = h0;
                        Vtl[base] = __float2bfloat16(l0f);
                        Vth[base + S_] = h1;        // d+1 row
                        Vtl[base + S_] = __float2bfloat16(l1f);
                    }
                }
            }
        }
    }
}

// ---------------------------------------------------------------------------
// Tensor-core flash attention. CTA = 128 q rows (8 warps x 16), key chunks
// of 64, online softmax in registers, split-bf16 on QK^T and PV.
// smem: K hi/lo [64][72] + V^T hi/lo [64][72] = 36.9 KB.
// ---------------------------------------------------------------------------
#define SKS 72

__global__ __launch_bounds__(256, 1)
void attn_mma_kernel(const __nv_bfloat16* __restrict__ qkv_hi,
                     const __nv_bfloat16* __restrict__ qkv_lo,
                     const __nv_bfloat16* __restrict__ vt_hi,
                     const __nv_bfloat16* __restrict__ vt_lo,
                     const float* __restrict__ pm_k,
                     const __nv_bfloat16* __restrict__ pmvt_hi,
                     const __nv_bfloat16* __restrict__ pmvt_lo,
                     __nv_bfloat16* __restrict__ ohi,
                     __nv_bfloat16* __restrict__ olo) {
    __shared__ __align__(16) __nv_bfloat16 sKh[64 * SKS];
    __shared__ __align__(16) __nv_bfloat16 sKl[64 * SKS];
    __shared__ __align__(16) __nv_bfloat16 sVh[64 * SKS];
    __shared__ __align__(16) __nv_bfloat16 sVl[64 * SKS];

    int tile = blockIdx.x;
    int h = tile % HEADS;
    int w = (tile / HEADS) % NW;
    int b = tile / (HEADS * NW);
    int q0 = blockIdx.y * 128;
    int tid = threadIdx.x, wid = tid >> 5, lane = tid & 31;
    int g = lane >> 2, tg = lane & 3;
    int wrow = wid * 16;
    int sq_base = b * S_ + w * SEG + q0 + wrow;

    // Q fragments (hi/lo), loaded once from global
    uint32_t qh[4][4], ql[4][4];
    {
        const __nv_bfloat16* r0h = qkv_hi + (size_t)(sq_base + g) * NQKV + h * DH;
        const __nv_bfloat16* r1h = qkv_hi + (size_t)(sq_base + g + 8) * NQKV + h * DH;
        const __nv_bfloat16* r0l = qkv_lo + (size_t)(sq_base + g) * NQKV + h * DH;
        const __nv_bfloat16* r1l = qkv_lo + (size_t)(sq_base + g + 8) * NQKV + h * DH;
#pragma unroll
        for (int ks = 0; ks < 4; ks++) {
            int c = ks * 16 + tg * 2;
            qh[ks][0] = *(const uint32_t*)(r0h + c);
            qh[ks][1] = *(const uint32_t*)(r1h + c);
            qh[ks][2] = *(const uint32_t*)(r0h + c + 8);
            qh[ks][3] = *(const uint32_t*)(r1h + c + 8);
            ql[ks][0] = *(const uint32_t*)(r0l + c);
            ql[ks][1] = *(const uint32_t*)(r1l + c);
            ql[ks][2] = *(const uint32_t*)(r0l + c + 8);
            ql[ks][3] = *(const uint32_t*)(r1l + c + 8);
        }
    }

    float oacc[8][4];
#pragma unroll
    for (int dt = 0; dt < 8; dt++)
#pragma unroll
        for (int q = 0; q < 4; q++) oacc[dt][q] = 0.f;
    float mrun[2] = {-1e30f, -1e30f};
    float lrun[2] = {0.f, 0.f};

    int qi0 = q0 + wrow + g;
    int qi1 = qi0 + 8;
    int qmax = q0 + wrow + 15;             // warp-uniform last q row
    int nch = (q0 + 128 + P_ + 63) / 64;   // causal chunk limit for this CTA

    for (int ch = 0; ch < nch; ch++) {
        int j0 = ch * 64;
        // Cooperative load: K chunk (row j, col d) and V^T chunk (row d, col j)
#pragma unroll
        for (int i = 0; i < 2; i++) {
            int e = tid * 2 + i;
            int r = e >> 3;               // K: j row   / V^T: d row
            int cg = (e & 7) * 8;         // K: d0      / V^T: j0'
            // --- K ---
            {
                int jg = j0 + r;
                uint4 vh, vl;
                if (jg < P_) {
                    const float* src = pm_k + ((h * P_ + jg) * DH + cg);
                    float f[8];
                    float4 f0 = *(const float4*)src;
                    float4 f1 = *(const float4*)(src + 4);
                    f[0] = f0.x; f[1] = f0.y; f[2] = f0.z; f[3] = f0.w;
                    f[4] = f1.x; f[5] = f1.y; f[6] = f1.z; f[7] = f1.w;
                    split8(f, vh, vl);
                } else if (jg < T_) {
                    size_t rowb = ((size_t)(b * S_ + w * SEG + jg - P_)) * NQKV
                                  + INNER + h * DH + cg;
                    vh = *(const uint4*)(qkv_hi + rowb);
                    vl = *(const uint4*)(qkv_lo + rowb);
                } else {
                    vh = make_uint4(0, 0, 0, 0);
                    vl = make_uint4(0, 0, 0, 0);
                }
                *(uint4*)&sKh[r * SKS + cg] = vh;
                *(uint4*)&sKl[r * SKS + cg] = vl;
            }
            // --- V^T ---
            {
                int jv = j0 + cg;   // 8 consecutive j share region (16-aligned)
                uint4 wh, wl;
                if (jv < P_) {
                    const __nv_bfloat16* sh = pmvt_hi + (h * DH + r) * P_ + jv;
                    const __nv_bfloat16* sl = pmvt_lo + (h * DH + r) * P_ + jv;
                    wh = *(const uint4*)sh;
                    wl = *(const uint4*)sl;
                } else if (jv < T_) {
                    size_t rb = ((size_t)((b * HEADS + h) * DH + r)) * S_
                                + w * SEG + jv - P_;
                    wh = *(const uint4*)(vt_hi + rb);
                    wl = *(const uint4*)(vt_lo + rb);
                } else {
                    wh = make_uint4(0, 0, 0, 0);
                    wl = make_uint4(0, 0, 0, 0);
                }
                *(uint4*)&sVh[r * SKS + cg] = wh;
                *(uint4*)&sVl[r * SKS + cg] = wl;
            }
        }
        __syncthreads();

        bool active = (j0 <= qmax + P_);   // warp-uniform: any unmasked key
        if (active) {
            // S = Q K^T (split: Qh*Kh + Qh*Kl + Ql*Kh)
            float s[8][4];
#pragma unroll
            for (int nt = 0; nt < 8; nt++) {
#pragma unroll
                for (int q = 0; q < 4; q++) s[nt][q] = 0.f;
#pragma unroll
                for (int ks = 0; ks < 4; ks++) {
                    int off = (nt * 8 + g) * SKS + ks * 16 + tg * 2;
                    uint32_t b0h = *(const uint32_t*)&sKh[off];
                    uint32_t b1h = *(const uint32_t*)&sKh[off + 8];
                    uint32_t b0l = *(const uint32_t*)&sKl[off];
                    uint32_t b1l = *(const uint32_t*)&sKl[off + 8];
                    MMA16816(s[nt], qh[ks][0], qh[ks][1], qh[ks][2], qh[ks][3], b0h, b1h);
                    MMA16816(s[nt], qh[ks][0], qh[ks][1], qh[ks][2], qh[ks][3], b0l, b1l);
                    MMA16816(s[nt], ql[ks][0], ql[ks][1], ql[ks][2], ql[ks][3], b0h, b1h);
                }
            }
            // Mask
#pragma unroll
            for (int nt = 0; nt < 8; nt++) {
                int jc = j0 + nt * 8 + tg * 2;
                if (jc > qi0 + P_)     s[nt][0] = -1e30f;
                if (jc + 1 > qi0 + P_) s[nt][1] = -1e30f;
                if (jc > qi1 + P_)     s[nt][2] = -1e30f;
                if (jc + 1 > qi1 + P_) s[nt][3] = -1e30f;
            }
            // Online softmax per row half
#pragma unroll
            for (int rh = 0; rh < 2; rh++) {
                float mloc = -1e30f;
#pragma unroll
                for (int nt = 0; nt < 8; nt++) {
                    mloc = fmaxf(mloc, s[nt][rh * 2]);
                    mloc = fmaxf(mloc, s[nt][rh * 2 + 1]);
                }
                mloc = fmaxf(mloc, __shfl_xor_sync(0xffffffffu, mloc, 1));
                mloc = fmaxf(mloc, __shfl_xor_sync(0xffffffffu, mloc, 2));
                float mnew = fmaxf(mrun[rh], mloc);
                float corr = __expf(mrun[rh] - mnew);
                float lsum = 0.f;
#pragma unroll
                for (int nt = 0; nt < 8; nt++) {
                    float p0 = __expf(s[nt][rh * 2] - mnew);
                    float p1 = __expf(s[nt][rh * 2 + 1] - mnew);
                    s[nt][rh * 2] = p0;
                    s[nt][rh * 2 + 1] = p1;
                    lsum += p0 + p1;
                }
                lsum += __shfl_xor_sync(0xffffffffu, lsum, 1);
                lsum += __shfl_xor_sync(0xffffffffu, lsum, 2);
                lrun[rh] = lrun[rh] * corr + lsum;
                mrun[rh] = mnew;
#pragma unroll
                for (int dt = 0; dt < 8; dt++) {
                    oacc[dt][rh * 2] *= corr;
                    oacc[dt][rh * 2 + 1] *= corr;
                }
            }
            // P fragments (hi/lo) + PV (Ph*Vh + Ph*Vl + Pl*Vh)
#pragma unroll
            for (int kj = 0; kj < 4; kj++) {
                float p00 = s[2 * kj][0], p01 = s[2 * kj][1];
                float p02 = s[2 * kj][2], p03 = s[2 * kj][3];
                float p10 = s[2 * kj + 1][0], p11 = s[2 * kj + 1][1];
                float p12 = s[2 * kj + 1][2], p13 = s[2 * kj + 1][3];
                uint32_t ah0 = packbf(p00, p01), ah1 = packbf(p02, p03);
                uint32_t ah2 = packbf(p10, p11), ah3 = packbf(p12, p13);
                float h00 = __bfloat162float(__float2bfloat16(p00));
                float h01 = __bfloat162float(__float2bfloat16(p01));
                float h02 = __bfloat162float(__float2bfloat16(p02));
                float h03 = __bfloat162float(__float2bfloat16(p03));
                float h10 = __bfloat162float(__float2bfloat16(p10));
                float h11 = __bfloat162float(__float2bfloat16(p11));
                float h12 = __bfloat162float(__float2bfloat16(p12));
                float h13 = __bfloat162float(__float2bfloat16(p13));
                uint32_t al0 = packbf(p00 - h00, p01 - h01);
                uint32_t al1 = packbf(p02 - h02, p03 - h03);
                uint32_t al2 = packbf(p10 - h10, p11 - h11);
                uint32_t al3 = packbf(p12 - h12, p13 - h13);
#pragma unroll
                for (int dt = 0; dt < 8; dt++) {
                    int off = (dt * 8 + g) * SKS + kj * 16 + tg * 2;
                    uint32_t b0h = *(const uint32_t*)&sVh[off];
                    uint32_t b1h = *(const uint32_t*)&sVh[off + 8];
                    uint32_t b0l = *(const uint32_t*)&sVl[off];
                    uint32_t b1l = *(const uint32_t*)&sVl[off + 8];
                    MMA16816(oacc[dt], ah0, ah1, ah2, ah3, b0h, b1h);
                    MMA16816(oacc[dt], ah0, ah1, ah2, ah3, b0l, b1l);
                    MMA16816(oacc[dt], al0, al1, al2, al3, b0h, b1h);
                }
            }
        }
        __syncthreads();
    }

    // Normalize + store bf16 hi/lo
    float inv0 = 1.f / lrun[0];
    float inv1 = 1.f / lrun[1];
#pragma unroll
    for (int rh = 0; rh < 2; rh++) {
        float inv = rh ? inv1 : inv0;
        size_t base = (size_t)(sq_base + g + rh * 8) * INNER + h * DH + tg * 2;
#pragma unroll
        for (int dt = 0; dt < 8; dt++) {
            float v0 = oacc[dt][rh * 2] * inv;
            float v1 = oacc[dt][rh * 2 + 1] * inv;
            __nv_bfloat16 h0 = __float2bfloat16(v0);
            __nv_bfloat16 h1 = __float2bfloat16(v1);
            float l0 = v0 - __bfloat162float(h0);
            float l1 = v1 - __bfloat162float(h1);
            *(uint32_t*)&ohi[base + dt * 8] =
                packbf(__bfloat162float(h0), __bfloat162float(h1));
            *(uint32_t*)&olo[base + dt * 8] = packbf(l0, l1);
        }
    }
}

// ---------------------------------------------------------------------------
// Launch
// ---------------------------------------------------------------------------
extern "C" void kernel_launch(void* const* d_in, const int* in_sizes, int n_in,
                              void* d_out, int out_size) {
    (void)in_sizes; (void)n_in; (void)out_size;
    const float* x      = (const float*)d_in[0];
    const float* gamma  = (const float*)d_in[1];
    const float* w_qkv  = (const float*)d_in[2];
    const float* w_out  = (const float*)d_in[3];
    const float* pm_k   = (const float*)d_in[4];
    const float* pm_v   = (const float*)d_in[5];
    float* out = (float*)d_out;

    __nv_bfloat16 *h_hi, *h_lo, *wq_hi, *wq_lo, *wo_hi, *wo_lo;
    __nv_bfloat16 *qkv_hi, *qkv_lo, *vt_hi, *vt_lo, *pmvt_hi, *pmvt_lo;
    __nv_bfloat16 *a_hi, *a_lo;
    cudaGetSymbolAddress((void**)&h_hi, g_h_hi);
    cudaGetSymbolAddress((void**)&h_lo, g_h_lo);
    cudaGetSymbolAddress((void**)&wq_hi, g_wqkvT_hi);
    cudaGetSymbolAddress((void**)&wq_lo, g_wqkvT_lo);
    cudaGetSymbolAddress((void**)&wo_hi, g_woutT_hi);
    cudaGetSymbolAddress((void**)&wo_lo, g_woutT_lo);
    cudaGetSymbolAddress((void**)&qkv_hi, g_qkv_hi);
    cudaGetSymbolAddress((void**)&qkv_lo, g_qkv_lo);
    cudaGetSymbolAddress((void**)&vt_hi, g_vt_hi);
    cudaGetSymbolAddress((void**)&vt_lo, g_vt_lo);
    cudaGetSymbolAddress((void**)&pmvt_hi, g_pmvt_hi);
    cudaGetSymbolAddress((void**)&pmvt_lo, g_pmvt_lo);
    cudaGetSymbolAddress((void**)&a_hi, g_attn_hi);
    cudaGetSymbolAddress((void**)&a_lo, g_attn_lo);

    // Weight prep (transpose + bf16 split)
    {
        dim3 blk(32, 8);
        dim3 g1(NQKV / 32, D_ / 32);
        transpose_split_kernel<<<g1, blk>>>(w_qkv, wq_hi, wq_lo, D_, NQKV);
        dim3 g2(D_ / 32, INNER / 32);
        transpose_split_kernel<<<g2, blk>>>(w_out, wo_hi, wo_lo, INNER, D_);
    }

    // pm_v transpose + split
    pmvt_kernel<<<(HEADS * P_ * DH + 255) / 256, 256>>>(pm_v, pmvt_hi, pmvt_lo);

    // RMSNorm + split
    rmsnorm_split_kernel<<<ROWS, 256>>>(x, gamma, h_hi, h_lo);

    // QKV projection -> bf16 hi/lo (Q scaled) + transposed V
    {
        dim3 grid(NQKV / 128, ROWS / 128);
        gemm_mma_kernel<1><<<grid, 256>>>(h_hi, h_lo, wq_hi, wq_lo,
                                          nullptr, qkv_hi, qkv_lo,
                                          vt_hi, vt_lo, NQKV);
    }

    // Flash attention (tensor cores)
    {
        dim3 grid(B_ * NW * HEADS, SEG / 128);
        attn_mma_kernel<<<grid, 256>>>(qkv_hi, qkv_lo, vt_hi, vt_lo,
                                       pm_k, pmvt_hi, pmvt_lo, a_hi, a_lo);
    }

    // Output projection -> fp32 d_out
    {
        dim3 grid(D_ / 128, ROWS / 128);
        gemm_mma_kernel<0><<<grid, 256>>>(a_hi, a_lo, wo_hi, wo_lo,
                                          out, nullptr, nullptr,
                                          nullptr, nullptr, D_);
    }
}